// round 16
// baseline (speedup 1.0000x reference)
#include <cuda_runtime.h>
#include <cstdint>

#define Nn   6144
#define FIN  256
#define FH   64
#define Hh   4
#define FO   32
#define JSPLIT 3
#define KS3  (Nn / JSPLIT)       // 2048
#define NW   (Nn / 32)           // 192
#define LOG2E 1.4426950408889634f

// ---------------- scratch ----------------
__device__ __align__(16) float    g_WT[FIN * FIN];       // Wcat^T [n=256][k=256]
__device__ __align__(16) uint32_t g_hT32[FIN * Nn];      // h^T, tf32-prerounded, j-permuted in 32-blocks
__device__ float    g_s1[Hh * Nn];
__device__ float    g_s2[Hh * Nn];
__device__ uint32_t g_adjbits[Nn * NW];
__device__ float    g_pnum[(size_t)JSPLIT * Nn * FIN];
__device__ float    g_pden[JSPLIT * Hh * Nn];
__device__ float    g_x2[Nn * FH];
__device__ float    g_h2[Nn * FO];
__device__ float    g_s1b[Nn];
__device__ float    g_s2b[Nn];
__device__ float    g_p2num[JSPLIT * Nn * FO];
__device__ float    g_p2den[JSPLIT * Nn];

// ---------------- helpers ----------------
__device__ __forceinline__ float ex2f(float x) {
    float y; asm("ex2.approx.f32 %0, %1;" : "=f"(y) : "f"(x)); return y;
}
__device__ __forceinline__ uint32_t f2tf32(float x) {
    uint32_t r; asm("cvt.rna.tf32.f32 %0, %1;" : "=r"(r) : "f"(x)); return r;
}
__device__ __forceinline__ void mma_tf32(float* c, const uint32_t* a, const uint32_t* b) {
    asm volatile(
        "mma.sync.aligned.m16n8k8.row.col.f32.tf32.tf32.f32 "
        "{%0,%1,%2,%3}, {%4,%5,%6,%7}, {%8,%9}, {%0,%1,%2,%3};\n"
        : "+f"(c[0]), "+f"(c[1]), "+f"(c[2]), "+f"(c[3])
        : "r"(a[0]), "r"(a[1]), "r"(a[2]), "r"(a[3]), "r"(b[0]), "r"(b[1]));
}
__device__ __forceinline__ uint32_t sptr(const void* p) {
    return (uint32_t)__cvta_generic_to_shared(p);
}
__device__ __forceinline__ void cp16(uint32_t dst, const void* src) {
    asm volatile("cp.async.ca.shared.global [%0], [%1], 16;" :: "r"(dst), "l"(src) : "memory");
}
#define CP_COMMIT() asm volatile("cp.async.commit_group;" ::: "memory")
#define CP_WAIT1()  asm volatile("cp.async.wait_group 1;" ::: "memory")

__device__ __forceinline__ float wc(float s1, float s2, uint32_t mask, int c) {
    float e = s1 + s2;
    e = fmaxf(e, 0.2f * e);
    float w = ex2f(e);
    return ((mask >> c) & 1u) ? w : 0.f;
}

// ---------------- Kprep: pack adjacency to bitmasks ----------------
__global__ __launch_bounds__(256) void kprep(const int* __restrict__ adj) {
    const int gw = (blockIdx.x * 256 + threadIdx.x) >> 5;
    const int lane = threadIdx.x & 31;
    int v = adj[(size_t)gw * 32 + lane];
    unsigned m = __ballot_sync(0xffffffffu, v > 0);
    if (lane == 0) g_adjbits[gw] = m;
}

// ---------------- KprepW: W_cat^T [n][k] ----------------
__global__ __launch_bounds__(256) void kprepW(const float* __restrict__ Wh) {
    int e = blockIdx.x * 256 + threadIdx.x;     // 65536
    int n = e >> 8, k = e & 255;
    g_WT[n * 256 + k] = Wh[(n >> 6) * (256 * 64) + k * 64 + (n & 63)];
}

// ---------------- K1: h = x @ Wcat via 3xTF32 mma (fp32-grade); fused transpose + scores ----------------
// grid 192 (32 rows/CTA), 256 thr = 8 warps (wy 2 x wx 4), warp tile 16x64, K-chunk 8.
// g_hT32 written with per-32-block column permutation pos = (t%4)*8 + t/4.
__global__ __launch_bounds__(256) void k1_mma(const float* __restrict__ x,
                                              const float* __restrict__ ah) {
    __shared__ __align__(16) float xs[2][32][12];
    __shared__ __align__(16) float Ws[2][256][12];
    __shared__ __align__(16) float Cs[16][264];
    __shared__ float sa[512];
    const int tid = threadIdx.x, lane = tid & 31, wid = tid >> 5;
    const int wy = wid >> 2, wx = wid & 3, tg = lane >> 2, tig = lane & 3;
    const int i0 = blockIdx.x * 32;
    sa[tid] = ah[tid]; sa[tid + 256] = ah[tid + 256];

    float acc[8][4] = {};

    auto stage = [&](int it, int b) {
        const int kk = it * 8;
#pragma unroll
        for (int c = 0; c < 2; ++c) {
            int ch = tid + c * 256;
            int n = ch >> 1, hf = ch & 1;
            cp16(sptr(&Ws[b][n][hf * 4]), &g_WT[n * 256 + kk + hf * 4]);
        }
        if (tid < 64) {
            int r = tid >> 1, hf = tid & 1;
            cp16(sptr(&xs[b][r][hf * 4]), &x[(size_t)(i0 + r) * 256 + kk + hf * 4]);
        }
    };

    stage(0, 0); CP_COMMIT();
    stage(1, 1); CP_COMMIT();

    for (int it = 0; it < 32; ++it) {
        const int b = it & 1;
        CP_WAIT1();
        __syncthreads();
        // A fragments: hi/lo split for 3xTF32
        const int m0 = wy * 16 + tg;
        float av[4] = { xs[b][m0][tig], xs[b][m0 + 8][tig],
                        xs[b][m0][tig + 4], xs[b][m0 + 8][tig + 4] };
        uint32_t Ah[4], Al[4];
#pragma unroll
        for (int u = 0; u < 4; ++u) {
            Ah[u] = f2tf32(av[u]);
            Al[u] = f2tf32(av[u] - __uint_as_float(Ah[u]));
        }
#pragma unroll
        for (int nt = 0; nt < 8; ++nt) {
            const int n = wx * 64 + nt * 8 + tg;
            float b0 = Ws[b][n][tig], b1 = Ws[b][n][tig + 4];
            uint32_t Bh[2] = { f2tf32(b0), f2tf32(b1) };
            uint32_t Bl[2] = { f2tf32(b0 - __uint_as_float(Bh[0])),
                               f2tf32(b1 - __uint_as_float(Bh[1])) };
            mma_tf32(acc[nt], Ah, Bh);
            mma_tf32(acc[nt], Al, Bh);
            mma_tf32(acc[nt], Ah, Bl);
        }
        __syncthreads();
        // always commit one group per iteration (keeps wait_group 1 semantics exact)
        if (it + 2 < 32) stage(it + 2, b);
        CP_COMMIT();
    }

    // epilogue: two 16-row phases through Cs
#pragma unroll
    for (int ph = 0; ph < 2; ++ph) {
        __syncthreads();
        if (wy == ph) {
#pragma unroll
            for (int nt = 0; nt < 8; ++nt) {
                int col = wx * 64 + nt * 8 + tig * 2;
                Cs[tg][col]     = acc[nt][0];
                Cs[tg][col + 1] = acc[nt][1];
                Cs[tg + 8][col]     = acc[nt][2];
                Cs[tg + 8][col + 1] = acc[nt][3];
            }
        }
        __syncthreads();
        // write h^T as tf32-prerounded bits, j-permuted within the 32-block
#pragma unroll
        for (int c = 0; c < 16; ++c) {
            int idx = tid + c * 256;          // 0..4095
            int f = idx >> 4, r = idx & 15;
            int t = ph * 16 + r;              // 0..31 within block
            int pos = (t & 3) * 8 + (t >> 2); // permutation
            g_hT32[(size_t)f * Nn + i0 + pos] = f2tf32(Cs[r][f]);
        }
        // scores (from fp32-grade h)
        if (tid < 64) {
            int r = tid & 15, hh = tid >> 4;
            float s1 = 0.f, s2 = 0.f;
#pragma unroll
            for (int f = 0; f < 64; ++f) {
                float v = Cs[r][hh * 64 + f];
                s1 = fmaf(v, sa[hh * 128 + f], s1);
                s2 = fmaf(v, sa[hh * 128 + 64 + f], s2);
            }
            int gi = i0 + ph * 16 + r;
            g_s1[hh * Nn + gi] = s1 * LOG2E;
            g_s2[hh * Nn + gi] = s2 * LOG2E;
        }
    }
}

// ---------------- K3: layer-1 attention via tf32 mma ----------------
// grid (96, 3), 512 thr = 16 warps = 4 heads x 4 i-quarters of 16 rows; 2 CTAs/SM.
// H tile: 256 rows x 32 words; word for logical col c at row*32 + (((c%4)*8 + c/4) ^ 4*(row&1)).
// (gmem is already column-permuted; staging applies only the row-parity XOR.)
__global__ void __launch_bounds__(512, 2) k3_mma() {
    extern __shared__ __align__(16) uint32_t Hdyn[];   // 2 x 8192 words = 64 KB
    const int tid = threadIdx.x, lane = tid & 31, wid = tid >> 5;
    const int h = wid >> 2, iq = wid & 3, tg = lane >> 2, tig = lane & 3;
    const int i0 = blockIdx.x * 64;
    const int js = blockIdx.y;
    const int jw0 = js * (KS3 / 32);
    const int NIT = KS3 / 32;   // 64
    const int xo = (tg & 1) * 4;

    float C[8][4] = {};
    float den0 = 0.f, den1 = 0.f;
    const float s1v0 = g_s1[h * Nn + i0 + iq * 16 + tg];
    const float s1v1 = g_s1[h * Nn + i0 + iq * 16 + tg + 8];

    auto stage = [&](int t, int b) {
        const int j0 = js * KS3 + t * 32;
#pragma unroll
        for (int c = 0; c < 4; ++c) {
            int ch = c * 512 + tid;
            int row = ch >> 3, g = ch & 7;
            uint32_t dst = b * 8192 + row * 32 + ((g * 4) ^ ((row & 1) * 4));
            cp16(sptr(&Hdyn[dst]), &g_hT32[(size_t)row * Nn + j0 + g * 4]);
        }
    };

    stage(0, 0); CP_COMMIT();
    stage(1, 1); CP_COMMIT();
    uint32_t mk0 = g_adjbits[(size_t)(i0 + iq * 16 + tg) * NW + jw0];
    uint32_t mk1 = g_adjbits[(size_t)(i0 + iq * 16 + tg + 8) * NW + jw0];

    for (int t = 0; t < NIT; ++t) {
        const int b = t & 1;
        const int j0 = js * KS3 + t * 32;
        CP_WAIT1();
        __syncthreads();
        uint32_t mkn0 = 0, mkn1 = 0;
        if (t + 1 < NIT) {
            mkn0 = g_adjbits[(size_t)(i0 + iq * 16 + tg) * NW + jw0 + t + 1];
            mkn1 = g_adjbits[(size_t)(i0 + iq * 16 + tg + 8) * NW + jw0 + t + 1];
        }
        // A fragments (raw fp32 bits; HW truncates to tf32)
        uint32_t A[4][4];
#pragma unroll
        for (int kc = 0; kc < 4; ++kc) {
            float s2a = __ldg(&g_s2[h * Nn + j0 + kc * 8 + tig]);
            float s2b = __ldg(&g_s2[h * Nn + j0 + kc * 8 + tig + 4]);
            const int c0 = kc * 8 + tig, c1 = c0 + 4;
            float w00 = wc(s1v0, s2a, mk0, c0);
            float w10 = wc(s1v1, s2a, mk1, c0);
            float w01 = wc(s1v0, s2b, mk0, c1);
            float w11 = wc(s1v1, s2b, mk1, c1);
            den0 += w00 + w01;
            den1 += w10 + w11;
            A[kc][0] = __float_as_uint(w00);
            A[kc][1] = __float_as_uint(w10);
            A[kc][2] = __float_as_uint(w01);
            A[kc][3] = __float_as_uint(w11);
        }
        const uint32_t* Hb = Hdyn + b * 8192;
#pragma unroll
        for (int nt = 0; nt < 8; ++nt) {
            const int rw = (h * 64 + nt * 8 + tg) * 32 + tig * 8;
            uint32_t L[8];
            *(uint4*)&L[0] = *(const uint4*)&Hb[rw + xo];        // logical d 0..3
            *(uint4*)&L[4] = *(const uint4*)&Hb[rw + (4 ^ xo)];  // logical d 4..7
#pragma unroll
            for (int kc = 0; kc < 4; ++kc)
                mma_tf32(C[nt], A[kc], &L[2 * kc]);
        }
        __syncthreads();
        if (t + 2 < NIT) stage(t + 2, b);
        CP_COMMIT();
        mk0 = mkn0; mk1 = mkn1;
    }

    // denominators: reduce over tig
    {
        float v = den0;
        v += __shfl_xor_sync(0xffffffffu, v, 1);
        v += __shfl_xor_sync(0xffffffffu, v, 2);
        float u = den1;
        u += __shfl_xor_sync(0xffffffffu, u, 1);
        u += __shfl_xor_sync(0xffffffffu, u, 2);
        if (tig == 0) {
            g_pden[(js * Hh + h) * Nn + i0 + iq * 16 + tg]     = v;
            g_pden[(js * Hh + h) * Nn + i0 + iq * 16 + tg + 8] = u;
        }
    }
    // numerators
    float* pn = g_pnum + (size_t)js * Nn * FIN;
    {
        const int r = i0 + iq * 16 + tg;
#pragma unroll
        for (int nt = 0; nt < 8; ++nt) {
            const int f = h * 64 + nt * 8 + tig * 2;
            *(float2*)&pn[(size_t)r * FIN + f]       = make_float2(C[nt][0], C[nt][1]);
            *(float2*)&pn[(size_t)(r + 8) * FIN + f] = make_float2(C[nt][2], C[nt][3]);
        }
    }
}

// ---------------- K3b: combine j-splits, normalize, elu, head-mean ----------------
__global__ __launch_bounds__(256) void k3b_combine() {
    const int idx = blockIdx.x * 256 + threadIdx.x;
    const int i = idx >> 6, f = idx & 63;
    float x2v = 0.f;
#pragma unroll
    for (int hd = 0; hd < Hh; ++hd) {
        float num = 0.f, dsum = 0.f;
#pragma unroll
        for (int js = 0; js < JSPLIT; ++js) {
            num  += g_pnum[(size_t)js * Nn * FIN + (size_t)i * FIN + hd * FH + f];
            dsum += g_pden[(js * Hh + hd) * Nn + i];
        }
        float o = num / dsum;
        o = (o > 0.f) ? o : (__expf(o) - 1.f);
        x2v += o;
    }
    g_x2[idx] = x2v * 0.25f;
}

// ---------------- K4: h2 = x2 @ W_out ----------------
__global__ __launch_bounds__(256) void k4_gemm2(const float* __restrict__ Wo) {
    __shared__ float Ws[64 * 32];
    __shared__ float xs[8][64];
    const int tid = threadIdx.x;
    const int i0 = blockIdx.x * 8;
    const int li = tid >> 5, f = tid & 31;
    for (int t = tid; t < 2048; t += 256) Ws[t] = Wo[t];
    for (int t = tid; t < 512; t += 256) xs[t >> 6][t & 63] = g_x2[(i0 + (t >> 6)) * 64 + (t & 63)];
    __syncthreads();
    float acc = 0.f;
#pragma unroll
    for (int k = 0; k < 64; ++k) acc = fmaf(xs[li][k], Ws[k * 32 + f], acc);
    g_h2[(i0 + li) * 32 + f] = acc;
}

// ---------------- K5: s1b/s2b ----------------
__global__ __launch_bounds__(256) void k5_scores2(const float* __restrict__ ao) {
    __shared__ float as[64];
    const int i = blockIdx.x * 256 + threadIdx.x;
    if (threadIdx.x < 64) as[threadIdx.x] = ao[threadIdx.x];
    __syncthreads();
    const float* hr = g_h2 + (size_t)i * 32;
    float s1 = 0.f, s2 = 0.f;
#pragma unroll
    for (int k = 0; k < 32; ++k) {
        float v = hr[k];
        s1 = fmaf(v, as[k], s1);
        s2 = fmaf(v, as[32 + k], s2);
    }
    g_s1b[i] = s1 * LOG2E;
    g_s2b[i] = s2 * LOG2E;
}

// ---------------- K6: layer-2 attention via mma.sync tf32 ----------------
#define KS6 (Nn / JSPLIT)
__global__ __launch_bounds__(256) void k6_mma() {
    __shared__ uint32_t Hs2[32][40];
    const int tid = threadIdx.x;
    const int lane = tid & 31, wid = tid >> 5;
    const int iq = wid & 3, fh = wid >> 2;
    const int tg = lane >> 2, tig = lane & 3;
    const int i0 = blockIdx.x * 64;
    const int js = blockIdx.y;
    const int jw0 = js * (KS6 / 32);

    float C[2][4] = {};
    float den[2] = {};
    float s1v[2];
    s1v[0] = g_s1b[i0 + iq * 16 + tg];
    s1v[1] = g_s1b[i0 + iq * 16 + tg + 8];

    for (int t = 0; t < KS6 / 32; ++t) {
        const int j0 = js * KS6 + t * 32;
        __syncthreads();
        {
            const int row = tid >> 3, q = tid & 7;
            float4 v = *(const float4*)&g_h2[(size_t)(j0 + row) * FO + q * 4];
            uint4 u = make_uint4(f2tf32(v.x), f2tf32(v.y), f2tf32(v.z), f2tf32(v.w));
            *(uint4*)&Hs2[row][q * 4] = u;
        }
        __syncthreads();
        uint32_t mk[2];
        mk[0] = g_adjbits[(size_t)(i0 + iq * 16 + tg) * NW + jw0 + t];
        mk[1] = g_adjbits[(size_t)(i0 + iq * 16 + tg + 8) * NW + jw0 + t];
        float s2v[4][2];
#pragma unroll
        for (int kc = 0; kc < 4; ++kc) {
            s2v[kc][0] = __ldg(&g_s2b[j0 + kc * 8 + tig]);
            s2v[kc][1] = __ldg(&g_s2b[j0 + kc * 8 + tig + 4]);
        }
#pragma unroll
        for (int kc = 0; kc < 4; ++kc) {
            uint32_t B[2][2];
#pragma unroll
            for (int nt = 0; nt < 2; ++nt) {
                int f = fh * 16 + nt * 8 + tg;
                B[nt][0] = Hs2[kc * 8 + tig][f];
                B[nt][1] = Hs2[kc * 8 + tig + 4][f];
            }
            const int c0 = kc * 8 + tig, c1 = c0 + 4;
            uint32_t A[4];
            float w00 = wc(s1v[0], s2v[kc][0], mk[0], c0);
            float w10 = wc(s1v[1], s2v[kc][0], mk[1], c0);
            float w01 = wc(s1v[0], s2v[kc][1], mk[0], c1);
            float w11 = wc(s1v[1], s2v[kc][1], mk[1], c1);
            den[0] += w00 + w01; den[1] += w10 + w11;
            A[0] = f2tf32(w00); A[1] = f2tf32(w10); A[2] = f2tf32(w01); A[3] = f2tf32(w11);
#pragma unroll
            for (int nt = 0; nt < 2; ++nt)
                mma_tf32(C[nt], A, B[nt]);
        }
    }
#pragma unroll
    for (int rr = 0; rr < 2; ++rr) {
        float v = den[rr];
        v += __shfl_xor_sync(0xffffffffu, v, 1);
        v += __shfl_xor_sync(0xffffffffu, v, 2);
        if (tig == 0 && fh == 0)
            g_p2den[js * Nn + i0 + iq * 16 + tg + rr * 8] = v;
    }
    float* pn = g_p2num + (size_t)js * Nn * FO;
    {
        int r = i0 + iq * 16 + tg;
#pragma unroll
        for (int nt = 0; nt < 2; ++nt) {
            int f = fh * 16 + nt * 8 + tig * 2;
            *(float2*)&pn[(size_t)r * FO + f]       = make_float2(C[nt][0], C[nt][1]);
            *(float2*)&pn[(size_t)(r + 8) * FO + f] = make_float2(C[nt][2], C[nt][3]);
        }
    }
}

// ---------------- K6b: combine, normalize, elu ----------------
__global__ __launch_bounds__(256) void k6b_combine(float* __restrict__ out) {
    const int idx = blockIdx.x * 256 + threadIdx.x;
    const int i = idx >> 5;
    float num = 0.f, den = 0.f;
#pragma unroll
    for (int js = 0; js < JSPLIT; ++js) {
        num += g_p2num[(size_t)js * Nn * FO + idx];
        den += g_p2den[js * Nn + i];
    }
    float o = num / den;
    o = (o > 0.f) ? o : (__expf(o) - 1.f);
    out[idx] = o;
}

// ---------------- launch ----------------
extern "C" void kernel_launch(void* const* d_in, const int* in_sizes, int n_in,
                              void* d_out, int out_size) {
    (void)in_sizes; (void)n_in; (void)out_size;
    const float* x   = (const float*)d_in[0];
    const int*   adj = (const int*)d_in[1];
    const float* Wh  = (const float*)d_in[2];
    const float* ah  = (const float*)d_in[3];
    const float* Wo  = (const float*)d_in[4];
    const float* ao  = (const float*)d_in[5];
    float* out = (float*)d_out;

    cudaFuncSetAttribute(k3_mma, cudaFuncAttributeMaxDynamicSharedMemorySize, 65536);

    kprep      <<<(Nn * NW) / 8, 256>>>(adj);
    kprepW     <<<256, 256>>>(Wh);
    k1_mma     <<<Nn / 32, 256>>>(x, ah);
    k3_mma     <<<dim3(Nn / 64, JSPLIT), 512, 65536>>>();
    k3b_combine<<<(Nn * FH) / 256, 256>>>();
    k4_gemm2   <<<Nn / 8, 256>>>(Wo);
    k5_scores2 <<<Nn / 256, 256>>>(ao);
    k6_mma     <<<dim3(Nn / 64, JSPLIT), 256>>>();
    k6b_combine<<<(Nn * FO) / 256, 256>>>(out);
}